// round 3
// baseline (speedup 1.0000x reference)
#include <cuda_runtime.h>
#include <math.h>

#define B_ 16
#define T_ 256
#define S_ 1024
#define E_ 1024
#define V_ 32000
#define NBLK 148
#define NTHR 512

// ------------------ scratch (device globals; no allocation allowed) -------------
__device__ float g_Xemb[T_*B_*E_];      // [t*B+b][e]
__device__ float g_Xz0[T_*B_*S_];
__device__ float g_Xr0[T_*B_*S_];
__device__ float g_Xn0[T_*B_*S_];
__device__ float g_H2[T_*B_*S_];        // layer-1 hidden per step
__device__ float g_WhT[6*S_*S_];        // transposed hidden weights [(j*3+g)*S + c][k]
__device__ float g_WxT1[3*S_*S_];       // transposed layer-1 input weights [g*S + c][k]
__device__ float g_h0[B_*S_];
__device__ float g_h1[B_*S_];
__device__ float g_zbuf[B_*S_];
__device__ float g_rhbuf[B_*S_];
__device__ unsigned int g_barcnt;

// ------------------ small utility kernels ---------------------------------------
__global__ void reset_bar_k() { g_barcnt = 0u; }

__global__ void embed_k(const int* __restrict__ x, const float* __restrict__ emb) {
    int idx = blockIdx.x * blockDim.x + threadIdx.x;
    const int total = T_ * B_ * (E_ / 4);
    const int stride = gridDim.x * blockDim.x;
    for (; idx < total; idx += stride) {
        int e4 = idx & (E_/4 - 1);          // E_/4 = 256
        int tb = idx >> 8;
        int t = tb >> 4, b = tb & 15;
        int tok = x[b * T_ + t];
        reinterpret_cast<float4*>(g_Xemb)[idx] =
            reinterpret_cast<const float4*>(emb)[(size_t)tok * (E_/4) + e4];
    }
}

// Transpose weights: hidden parts (both layers, 3 gates) and layer-1 input parts.
__global__ void prep_k(const float* __restrict__ Wz, const float* __restrict__ Wr,
                       const float* __restrict__ Wn) {
    const int SS = S_ * S_;
    const int total = 6 * SS + 3 * SS;
    int idx = blockIdx.x * blockDim.x + threadIdx.x;
    const int stride = gridDim.x * blockDim.x;
    for (; idx < total; idx += stride) {
        if (idx < 6 * SS) {
            int k = idx & (S_ - 1);
            int c = (idx >> 10) & (S_ - 1);
            int t20 = idx >> 20;            // j*3 + g, 0..5
            int j = t20 / 3, g = t20 - 3 * j;
            const float* W = (g == 0) ? Wz : (g == 1) ? Wr : Wn;
            g_WhT[idx] = W[((size_t)(j * (E_ + S_) + E_ + k)) * S_ + c];
        } else {
            int i2 = idx - 6 * SS;
            int k = i2 & (S_ - 1);
            int c = (i2 >> 10) & (S_ - 1);
            int g = i2 >> 20;               // 0..2
            const float* W = (g == 0) ? Wz : (g == 1) ? Wr : Wn;
            g_WxT1[i2] = W[((size_t)(1 * (E_ + S_) + k)) * S_ + c];
        }
    }
}

// ------------------ generic fp32 SGEMM: C = A[M,K] * B[K,N] + bias ---------------
// A row-major ld=K, B row-major ld=N. remap=1: output row m -> (m%16)*T_ + m/16.
__global__ __launch_bounds__(256) void sgemm_bias(
    const float* __restrict__ A, const float* __restrict__ Bm,
    const float* __restrict__ bias, float* __restrict__ C,
    int M, int N, int K, int remap)
{
    __shared__ float As[8][128];
    __shared__ float Bs[8][128];
    const int tid = threadIdx.x;
    const int bx = blockIdx.x, by = blockIdx.y;
    const int tx = tid & 15, ty = tid >> 4;
    const int arow = tid >> 1, acol = (tid & 1) * 4;
    const int brow = tid >> 5, bcol = (tid & 31) * 4;
    const float* Ab = A + (size_t)(by * 128) * K;
    const float* Bb = Bm + bx * 128;

    float acc[8][8];
#pragma unroll
    for (int i = 0; i < 8; i++)
#pragma unroll
        for (int j = 0; j < 8; j++) acc[i][j] = 0.f;

    for (int k0 = 0; k0 < K; k0 += 8) {
        float4 a4 = *reinterpret_cast<const float4*>(Ab + (size_t)arow * K + k0 + acol);
        float4 b4 = *reinterpret_cast<const float4*>(Bb + (size_t)(k0 + brow) * N + bcol);
        __syncthreads();
        As[acol + 0][arow] = a4.x;
        As[acol + 1][arow] = a4.y;
        As[acol + 2][arow] = a4.z;
        As[acol + 3][arow] = a4.w;
        *reinterpret_cast<float4*>(&Bs[brow][bcol]) = b4;
        __syncthreads();
#pragma unroll
        for (int kk = 0; kk < 8; kk++) {
            float ar[8], br[8];
            *reinterpret_cast<float4*>(&ar[0]) = *reinterpret_cast<const float4*>(&As[kk][ty * 8]);
            *reinterpret_cast<float4*>(&ar[4]) = *reinterpret_cast<const float4*>(&As[kk][ty * 8 + 4]);
            *reinterpret_cast<float4*>(&br[0]) = *reinterpret_cast<const float4*>(&Bs[kk][tx * 8]);
            *reinterpret_cast<float4*>(&br[4]) = *reinterpret_cast<const float4*>(&Bs[kk][tx * 8 + 4]);
#pragma unroll
            for (int i = 0; i < 8; i++)
#pragma unroll
                for (int j = 0; j < 8; j++)
                    acc[i][j] = fmaf(ar[i], br[j], acc[i][j]);
        }
    }

#pragma unroll
    for (int i = 0; i < 8; i++) {
        int m = by * 128 + ty * 8 + i;
        int row = remap ? ((m & 15) * T_ + (m >> 4)) : m;
        float* Crow = C + (size_t)row * N + bx * 128 + tx * 8;
        const float* bvec = bias + bx * 128 + tx * 8;
        float4 o0, o1;
        o0.x = acc[i][0] + bvec[0]; o0.y = acc[i][1] + bvec[1];
        o0.z = acc[i][2] + bvec[2]; o0.w = acc[i][3] + bvec[3];
        o1.x = acc[i][4] + bvec[4]; o1.y = acc[i][5] + bvec[5];
        o1.z = acc[i][6] + bvec[6]; o1.w = acc[i][7] + bvec[7];
        *reinterpret_cast<float4*>(Crow)     = o0;
        *reinterpret_cast<float4*>(Crow + 4) = o1;
    }
}

// ------------------ persistent recurrence kernel --------------------------------
__device__ __forceinline__ float warp_sum(float v) {
#pragma unroll
    for (int o = 16; o; o >>= 1) v += __shfl_xor_sync(0xffffffffu, v, o);
    return v;
}

__device__ __forceinline__ void gsync(unsigned int& target) {
    __syncthreads();
    if (threadIdx.x == 0) {
        __threadfence();
        target += gridDim.x;
        atomicAdd(&g_barcnt, 1u);
        const unsigned int tg = target;
        volatile unsigned int* p = &g_barcnt;
        while (*p < tg) { }
        __threadfence();
    }
    __syncthreads();
}

__device__ __forceinline__ void dot_part(const float* __restrict__ wrow,
                                         const float* __restrict__ sh,
                                         int lane, float acc[16]) {
    const float4* w4 = reinterpret_cast<const float4*>(wrow);
#pragma unroll 2
    for (int kk = 0; kk < S_ / 4; kk += 32) {
        float4 w = w4[kk + lane];
        int kb = (kk + lane) * 4;
#pragma unroll
        for (int b = 0; b < 16; b++) {
            float4 h = *reinterpret_cast<const float4*>(sh + b * S_ + kb);
            acc[b] = fmaf(w.x, h.x, acc[b]);
            acc[b] = fmaf(w.y, h.y, acc[b]);
            acc[b] = fmaf(w.z, h.z, acc[b]);
            acc[b] = fmaf(w.w, h.w, acc[b]);
        }
    }
}

__device__ __forceinline__ void load_sh(float* dst, const float* src, int tid, int nthr) {
    const float4* s4 = reinterpret_cast<const float4*>(src);
    float4* d4 = reinterpret_cast<float4*>(dst);
    for (int i = tid; i < B_ * S_ / 4; i += nthr) d4[i] = __ldcg(s4 + i);
}

__global__ __launch_bounds__(NTHR, 1) void gru_recur(
    const float* __restrict__ bz, const float* __restrict__ br,
    const float* __restrict__ bn, float* __restrict__ hout)
{
    extern __shared__ float sh[];
    float* shA = sh;              // B_*S_ floats
    float* shB = sh + B_ * S_;    // B_*S_ floats
    const int tid = threadIdx.x;
    const int nthr = blockDim.x;
    const int gtid = blockIdx.x * nthr + tid;
    const int gthreads = gridDim.x * nthr;
    const int lane = tid & 31;
    const int gwarp = gtid >> 5;
    const int nwarps = gthreads >> 5;
    unsigned int bar_target = 0;

    // h = 0
    for (int i = gtid; i < B_ * S_; i += gthreads) {
        __stcg(&g_h0[i], 0.f);
        __stcg(&g_h1[i], 0.f);
    }
    for (int i = tid; i < B_ * S_; i += nthr) shA[i] = 0.f;
    gsync(bar_target);

    for (int t = 0; t < T_; ++t) {
        // ---- stage A0: layer0 z,r (shA holds h0) ----
        for (int u = gwarp; u < 2 * S_; u += nwarps) {
            int c = u & (S_ - 1);
            int g = u >> 10;
            const float* wrow = g_WhT + ((size_t)g * S_ + c) * S_;
            float acc[16];
#pragma unroll
            for (int b = 0; b < 16; b++) acc[b] = 0.f;
            dot_part(wrow, shA, lane, acc);
#pragma unroll
            for (int b = 0; b < 16; b++) {
                float s = warp_sum(acc[b]);
                if (lane == b) {
                    const float* base = g ? g_Xr0 : g_Xz0;
                    float pre = base[(t * B_ + b) * S_ + c] + s;
                    float sg = 1.f / (1.f + __expf(-pre));
                    if (g == 0) __stcg(&g_zbuf[b * S_ + c], sg);
                    else        __stcg(&g_rhbuf[b * S_ + c], sg * shA[b * S_ + c]);
                }
            }
        }
        gsync(bar_target);
        load_sh(shA, g_rhbuf, tid, nthr);   // shA <- r*h0
        __syncthreads();

        // ---- stage B0: layer0 n + h0 update ----
        for (int u = gwarp; u < S_; u += nwarps) {
            int c = u;
            const float* wrow = g_WhT + ((size_t)2 * S_ + c) * S_;
            float acc[16];
#pragma unroll
            for (int b = 0; b < 16; b++) acc[b] = 0.f;
            dot_part(wrow, shA, lane, acc);
#pragma unroll
            for (int b = 0; b < 16; b++) {
                float s = warp_sum(acc[b]);
                if (lane == b) {
                    float pre = g_Xn0[(t * B_ + b) * S_ + c] + s;
                    float n = tanhf(pre);
                    float ho = __ldcg(&g_h0[b * S_ + c]);
                    float z  = __ldcg(&g_zbuf[b * S_ + c]);
                    float hn = ho + z * (n - ho);
                    __stcg(&g_h0[b * S_ + c], hn);
                }
            }
        }
        gsync(bar_target);
        load_sh(shA, g_h0, tid, nthr);      // shA <- h0(new) (layer1 input)
        load_sh(shB, g_h1, tid, nthr);      // shB <- h1
        __syncthreads();

        // ---- stage A1: layer1 z,r ----
        for (int u = gwarp; u < 2 * S_; u += nwarps) {
            int c = u & (S_ - 1);
            int g = u >> 10;
            const float* wx = g_WxT1 + ((size_t)g * S_ + c) * S_;
            const float* wh = g_WhT + ((size_t)(3 + g) * S_ + c) * S_;
            float acc[16];
#pragma unroll
            for (int b = 0; b < 16; b++) acc[b] = 0.f;
            dot_part(wx, shA, lane, acc);
            dot_part(wh, shB, lane, acc);
#pragma unroll
            for (int b = 0; b < 16; b++) {
                float s = warp_sum(acc[b]);
                if (lane == b) {
                    const float* bias = g ? br : bz;
                    float pre = bias[S_ + c] + s;
                    float sg = 1.f / (1.f + __expf(-pre));
                    if (g == 0) __stcg(&g_zbuf[b * S_ + c], sg);
                    else        __stcg(&g_rhbuf[b * S_ + c], sg * shB[b * S_ + c]);
                }
            }
        }
        gsync(bar_target);
        load_sh(shB, g_rhbuf, tid, nthr);   // shB <- r1*h1 (shA keeps h0new)
        __syncthreads();

        // ---- stage B1: layer1 n + h1 update + H2 store ----
        for (int u = gwarp; u < S_; u += nwarps) {
            int c = u;
            const float* wx = g_WxT1 + ((size_t)2 * S_ + c) * S_;
            const float* wh = g_WhT + ((size_t)5 * S_ + c) * S_;
            float acc[16];
#pragma unroll
            for (int b = 0; b < 16; b++) acc[b] = 0.f;
            dot_part(wx, shA, lane, acc);
            dot_part(wh, shB, lane, acc);
#pragma unroll
            for (int b = 0; b < 16; b++) {
                float s = warp_sum(acc[b]);
                if (lane == b) {
                    float pre = bn[S_ + c] + s;
                    float n = tanhf(pre);
                    float ho = __ldcg(&g_h1[b * S_ + c]);
                    float z  = __ldcg(&g_zbuf[b * S_ + c]);
                    float hn = ho + z * (n - ho);
                    __stcg(&g_h1[b * S_ + c], hn);
                    __stcg(&g_H2[(t * B_ + b) * S_ + c], hn);
                }
            }
        }
        gsync(bar_target);
    }

    if (hout) {
        for (int i = gtid; i < B_ * S_; i += gthreads) {
            hout[i]            = __ldcg(&g_h0[i]);
            hout[B_ * S_ + i]  = __ldcg(&g_h1[i]);
        }
    }
}

// ------------------ launch --------------------------------------------------------
extern "C" void kernel_launch(void* const* d_in, const int* in_sizes, int n_in,
                              void* d_out, int out_size) {
    const int*   x   = (const int*)  d_in[0];
    const float* emb = (const float*)d_in[1];
    const float* Wz  = (const float*)d_in[2];
    const float* bz  = (const float*)d_in[3];
    const float* Wr  = (const float*)d_in[4];
    const float* br  = (const float*)d_in[5];
    const float* Wn  = (const float*)d_in[6];
    const float* bn  = (const float*)d_in[7];
    const float* Wo  = (const float*)d_in[8];
    const float* bo  = (const float*)d_in[9];
    float* out = (float*)d_out;

    (void)in_sizes; (void)n_in;

    cudaFuncSetAttribute(gru_recur, cudaFuncAttributeMaxDynamicSharedMemorySize,
                         2 * B_ * S_ * (int)sizeof(float));

    float *Xemb, *Xz0, *Xr0, *Xn0, *H2;
    cudaGetSymbolAddress((void**)&Xemb, g_Xemb);
    cudaGetSymbolAddress((void**)&Xz0, g_Xz0);
    cudaGetSymbolAddress((void**)&Xr0, g_Xr0);
    cudaGetSymbolAddress((void**)&Xn0, g_Xn0);
    cudaGetSymbolAddress((void**)&H2,  g_H2);

    float* hout = nullptr;
    long long need = (long long)B_ * T_ * V_ + 2LL * B_ * S_;
    if ((long long)out_size >= need) hout = out + (size_t)B_ * T_ * V_;

    reset_bar_k<<<1, 1>>>();
    prep_k<<<4608, 256>>>(Wz, Wr, Wn);
    embed_k<<<1024, 256>>>(x, emb);

    // layer-0 input projections: [4096,1024] @ [1024,1024] + bias
    dim3 gproj(S_ / 128, (T_ * B_) / 128);   // (8, 32)
    sgemm_bias<<<gproj, 256>>>(Xemb, Wz, bz, Xz0, T_ * B_, S_, E_, 0);
    sgemm_bias<<<gproj, 256>>>(Xemb, Wr, br, Xr0, T_ * B_, S_, E_, 0);
    sgemm_bias<<<gproj, 256>>>(Xemb, Wn, bn, Xn0, T_ * B_, S_, E_, 0);

    // sequential recurrence (persistent, grid-synced)
    gru_recur<<<NBLK, NTHR, 2 * B_ * S_ * sizeof(float)>>>(bz, br, bn, hout);

    // final vocab projection: [4096,1024] @ [1024,32000] + bias, rows remapped to [B,T,V]
    dim3 gout(V_ / 128, (T_ * B_) / 128);    // (250, 32)
    sgemm_bias<<<gout, 256>>>(H2, Wo, bo, out, T_ * B_, V_, S_, 1);
}

// round 4
// speedup vs baseline: 1.5258x; 1.5258x over previous
#include <cuda_runtime.h>
#include <math.h>

#define B_ 16
#define T_ 256
#define S_ 1024
#define E_ 1024
#define V_ 32000
#define NBLK 148
#define NTHR 512

// ------------------ scratch (device globals; no allocation allowed) -------------
__device__ float g_Xemb[T_*B_*E_];      // embeddings; later reused as H1 (layer-0 outputs)
__device__ float g_Xz0[T_*B_*S_];       // gate preactivations (input side + bias)
__device__ float g_Xr0[T_*B_*S_];
__device__ float g_Xn0[T_*B_*S_];
__device__ float g_H2[T_*B_*S_];        // layer-1 hidden per step
__device__ float g_WhT[6*S_*S_];        // transposed hidden weights [(j*3+g)*S + c][k]
__device__ float g_hb0[B_*S_];
__device__ float g_hb1[B_*S_];
__device__ float g_zbuf[B_*S_];
__device__ float g_rhbuf[B_*S_];
__device__ unsigned int g_flags[256];

// ------------------ small utility kernels ---------------------------------------
__global__ void reset_k() {
    if (threadIdx.x < 256) g_flags[threadIdx.x] = 0u;
}

__global__ void embed_k(const int* __restrict__ x, const float* __restrict__ emb) {
    int idx = blockIdx.x * blockDim.x + threadIdx.x;
    const int total = T_ * B_ * (E_ / 4);
    const int stride = gridDim.x * blockDim.x;
    for (; idx < total; idx += stride) {
        int e4 = idx & (E_/4 - 1);
        int tb = idx >> 8;
        int t = tb >> 4, b = tb & 15;
        int tok = x[b * T_ + t];
        reinterpret_cast<float4*>(g_Xemb)[idx] =
            reinterpret_cast<const float4*>(emb)[(size_t)tok * (E_/4) + e4];
    }
}

// Transpose hidden weights (both layers, 3 gates): g_WhT[(j*3+g)*S + c][k]
__global__ void prep_k(const float* __restrict__ Wz, const float* __restrict__ Wr,
                       const float* __restrict__ Wn) {
    const int SS = S_ * S_;
    const int total = 6 * SS;
    int idx = blockIdx.x * blockDim.x + threadIdx.x;
    const int stride = gridDim.x * blockDim.x;
    for (; idx < total; idx += stride) {
        int k = idx & (S_ - 1);
        int c = (idx >> 10) & (S_ - 1);
        int t20 = idx >> 20;            // j*3 + g, 0..5
        int j = t20 / 3, g = t20 - 3 * j;
        const float* W = (g == 0) ? Wz : (g == 1) ? Wr : Wn;
        g_WhT[idx] = W[((size_t)(j * (E_ + S_) + E_ + k)) * S_ + c];
    }
}

// ------------------ generic fp32 SGEMM: C = A[M,K] * B[K,N] + bias ---------------
// A row-major ld=K, B row-major ld=N. remap=1: output row m -> (m%16)*T_ + m/16.
__global__ __launch_bounds__(256) void sgemm_bias(
    const float* __restrict__ A, const float* __restrict__ Bm,
    const float* __restrict__ bias, float* __restrict__ C,
    int M, int N, int K, int remap)
{
    __shared__ float As[8][128];
    __shared__ float Bs[8][128];
    const int tid = threadIdx.x;
    const int bx = blockIdx.x, by = blockIdx.y;
    const int tx = tid & 15, ty = tid >> 4;
    const int arow = tid >> 1, acol = (tid & 1) * 4;
    const int brow = tid >> 5, bcol = (tid & 31) * 4;
    const float* Ab = A + (size_t)(by * 128) * K;
    const float* Bb = Bm + bx * 128;

    float acc[8][8];
#pragma unroll
    for (int i = 0; i < 8; i++)
#pragma unroll
        for (int j = 0; j < 8; j++) acc[i][j] = 0.f;

    // prefetch first tile
    float4 a4 = *reinterpret_cast<const float4*>(Ab + (size_t)arow * K + acol);
    float4 b4 = *reinterpret_cast<const float4*>(Bb + (size_t)brow * N + bcol);

    for (int k0 = 0; k0 < K; k0 += 8) {
        __syncthreads();
        As[acol + 0][arow] = a4.x;
        As[acol + 1][arow] = a4.y;
        As[acol + 2][arow] = a4.z;
        As[acol + 3][arow] = a4.w;
        *reinterpret_cast<float4*>(&Bs[brow][bcol]) = b4;
        __syncthreads();
        if (k0 + 8 < K) {  // prefetch next tile, overlapped with compute below
            a4 = *reinterpret_cast<const float4*>(Ab + (size_t)arow * K + (k0 + 8) + acol);
            b4 = *reinterpret_cast<const float4*>(Bb + (size_t)(k0 + 8 + brow) * N + bcol);
        }
#pragma unroll
        for (int kk = 0; kk < 8; kk++) {
            float ar[8], br[8];
            *reinterpret_cast<float4*>(&ar[0]) = *reinterpret_cast<const float4*>(&As[kk][ty * 8]);
            *reinterpret_cast<float4*>(&ar[4]) = *reinterpret_cast<const float4*>(&As[kk][ty * 8 + 4]);
            *reinterpret_cast<float4*>(&br[0]) = *reinterpret_cast<const float4*>(&Bs[kk][tx * 8]);
            *reinterpret_cast<float4*>(&br[4]) = *reinterpret_cast<const float4*>(&Bs[kk][tx * 8 + 4]);
#pragma unroll
            for (int i = 0; i < 8; i++)
#pragma unroll
                for (int j = 0; j < 8; j++)
                    acc[i][j] = fmaf(ar[i], br[j], acc[i][j]);
        }
    }

#pragma unroll
    for (int i = 0; i < 8; i++) {
        int m = by * 128 + ty * 8 + i;
        int row = remap ? ((m & 15) * T_ + (m >> 4)) : m;
        float* Crow = C + (size_t)row * N + bx * 128 + tx * 8;
        const float* bvec = bias + bx * 128 + tx * 8;
        float4 o0, o1;
        o0.x = acc[i][0] + bvec[0]; o0.y = acc[i][1] + bvec[1];
        o0.z = acc[i][2] + bvec[2]; o0.w = acc[i][3] + bvec[3];
        o1.x = acc[i][4] + bvec[4]; o1.y = acc[i][5] + bvec[5];
        o1.z = acc[i][6] + bvec[6]; o1.w = acc[i][7] + bvec[7];
        *reinterpret_cast<float4*>(Crow)     = o0;
        *reinterpret_cast<float4*>(Crow + 4) = o1;
    }
}

// ------------------ persistent single-layer recurrence ---------------------------
// Flag barrier: each block posts a monotonic epoch to its own slot (no atomics),
// warp 0 polls all slots coalesced.
__device__ __forceinline__ void flag_barrier(unsigned int e) {
    __syncthreads();
    if (threadIdx.x == 0) {
        __threadfence();
        *((volatile unsigned int*)&g_flags[blockIdx.x]) = e;
    }
    if (threadIdx.x < 32) {
        const int lane = threadIdx.x;
        for (;;) {
            bool ok = true;
            for (int i = lane; i < (int)gridDim.x; i += 32)
                ok &= (*((volatile const unsigned int*)&g_flags[i]) >= e);
            if (__all_sync(0xffffffffu, ok)) break;
            __nanosleep(200);
        }
        __threadfence();
    }
    __syncthreads();
}

__device__ __forceinline__ void load_sh(float* dst, const float* src, int tid, int nthr) {
    const float4* s4 = reinterpret_cast<const float4*>(src);
    float4* d4 = reinterpret_cast<float4*>(dst);
#pragma unroll
    for (int i = tid; i < B_ * S_ / 4; i += nthr) d4[i] = __ldcg(s4 + i);
}

// Dual dot over smem h: acc[0..15] vs w0, acc[16..31] vs w1, for 16 batches.
__device__ __forceinline__ void dual_dot(const float* __restrict__ w0row,
                                         const float* __restrict__ w1row,
                                         const float* __restrict__ sh,
                                         int lane, float acc[32]) {
    const float4* w04 = reinterpret_cast<const float4*>(w0row);
    const float4* w14 = reinterpret_cast<const float4*>(w1row);
#pragma unroll
    for (int kk = 0; kk < 8; kk++) {
        float4 a = w04[kk * 32 + lane];
        float4 c = w14[kk * 32 + lane];
        int kb = (kk * 32 + lane) * 4;
#pragma unroll
        for (int b = 0; b < 16; b++) {
            float4 h = *reinterpret_cast<const float4*>(sh + b * S_ + kb);
            acc[b]      = fmaf(a.x, h.x, acc[b]);
            acc[b]      = fmaf(a.y, h.y, acc[b]);
            acc[b]      = fmaf(a.z, h.z, acc[b]);
            acc[b]      = fmaf(a.w, h.w, acc[b]);
            acc[16 + b] = fmaf(c.x, h.x, acc[16 + b]);
            acc[16 + b] = fmaf(c.y, h.y, acc[16 + b]);
            acc[16 + b] = fmaf(c.z, h.z, acc[16 + b]);
            acc[16 + b] = fmaf(c.w, h.w, acc[16 + b]);
        }
    }
}

// Folding butterfly: reduce 32 values across 32 lanes in 31 shuffles.
// Post-condition: lane l holds the full warp-sum of acc[l].
__device__ __forceinline__ float reduce32(float acc[32], int lane) {
    int cnt = 32;
#pragma unroll
    for (int off = 16; off >= 1; off >>= 1) {
        const bool up = (lane & off) != 0;
        const int half = cnt >> 1;
#pragma unroll
        for (int i = 0; i < 16; i++) {
            if (i < half) {
                float send = up ? acc[i] : acc[i + half];
                float recv = __shfl_xor_sync(0xffffffffu, send, off);
                acc[i] = (up ? acc[i + half] : acc[i]) + recv;
            }
        }
        cnt = half;
    }
    return acc[0];
}

__global__ __launch_bounds__(NTHR, 1) void gru_pass(
    const float* __restrict__ Xz, const float* __restrict__ Xr,
    const float* __restrict__ Xn, const float* __restrict__ WhT,
    float* __restrict__ hbuf, float* __restrict__ Hseq, unsigned int ebase)
{
    extern __shared__ float sh[];
    float* shA = sh;              // h   (B_*S_ floats)
    float* shB = sh + B_ * S_;    // r*h
    const int tid = threadIdx.x;
    const int lane = tid & 31;
    const int wib = tid >> 5;                 // warp in block, 0..15
    const int bid = blockIdx.x;
    const int pA = wib * NBLK + bid;          // stage-A pair: column pA, gates z&r
    const int pB = pA;                        // stage-B pair: n-columns 2pB, 2pB+1

    // h = 0 locally (no cross-block init needed)
    for (int i = tid; i < B_ * S_; i += NTHR) shA[i] = 0.f;
    __syncthreads();

    for (int t = 0; t < T_; ++t) {
        // ---- stage A: z and r at column pA ----
        if (pA < S_) {
            const float* w0 = WhT + ((size_t)0 * S_ + pA) * S_;   // Whz row
            const float* w1 = WhT + ((size_t)1 * S_ + pA) * S_;   // Whr row
            float acc[32];
#pragma unroll
            for (int i = 0; i < 32; i++) acc[i] = 0.f;
            dual_dot(w0, w1, shA, lane, acc);
            float s = reduce32(acc, lane);
            int b = lane & 15;
            const float* Xg = (lane < 16) ? Xz : Xr;
            float pre = __ldcg(&Xg[((size_t)t * B_ + b) * S_ + pA]) + s;
            float sg = 1.f / (1.f + __expf(-pre));
            if (lane < 16) __stcg(&g_zbuf[b * S_ + pA], sg);
            else           __stcg(&g_rhbuf[b * S_ + pA], sg * shA[b * S_ + pA]);
        }
        flag_barrier(ebase + 2 * t + 1);
        load_sh(shB, g_rhbuf, tid, NTHR);
        __syncthreads();

        // ---- stage B: n at columns 2pB, 2pB+1; h update ----
        if (pB < S_ / 2) {
            const int c0 = 2 * pB;
            const float* w0 = WhT + ((size_t)2 * S_ + c0) * S_;       // Whn rows
            const float* w1 = WhT + ((size_t)2 * S_ + c0 + 1) * S_;
            float acc[32];
#pragma unroll
            for (int i = 0; i < 32; i++) acc[i] = 0.f;
            dual_dot(w0, w1, shB, lane, acc);
            float s = reduce32(acc, lane);
            int b = lane & 15;
            int col = c0 + (lane >> 4);
            float pre = __ldcg(&Xn[((size_t)t * B_ + b) * S_ + col]) + s;
            float n = tanhf(pre);
            float ho = shA[b * S_ + col];
            float z  = __ldcg(&g_zbuf[b * S_ + col]);
            float hn = ho + z * (n - ho);
            __stcg(&hbuf[b * S_ + col], hn);
            __stcg(&Hseq[((size_t)t * B_ + b) * S_ + col], hn);
        }
        flag_barrier(ebase + 2 * t + 2);
        load_sh(shA, hbuf, tid, NTHR);
        __syncthreads();
    }
}

__global__ void copy_h_k(float* __restrict__ hout) {
    int i = blockIdx.x * blockDim.x + threadIdx.x;
    if (i < B_ * S_) {
        hout[i]            = g_hb0[i];
        hout[B_ * S_ + i]  = g_hb1[i];
    }
}

// ------------------ launch --------------------------------------------------------
extern "C" void kernel_launch(void* const* d_in, const int* in_sizes, int n_in,
                              void* d_out, int out_size) {
    const int*   x   = (const int*)  d_in[0];
    const float* emb = (const float*)d_in[1];
    const float* Wz  = (const float*)d_in[2];
    const float* bz  = (const float*)d_in[3];
    const float* Wr  = (const float*)d_in[4];
    const float* br  = (const float*)d_in[5];
    const float* Wn  = (const float*)d_in[6];
    const float* bn  = (const float*)d_in[7];
    const float* Wo  = (const float*)d_in[8];
    const float* bo  = (const float*)d_in[9];
    float* out = (float*)d_out;
    (void)in_sizes; (void)n_in;

    const int smem = 2 * B_ * S_ * (int)sizeof(float);   // 128 KB
    cudaFuncSetAttribute(gru_pass, cudaFuncAttributeMaxDynamicSharedMemorySize, smem);

    float *Xemb, *Xz0, *Xr0, *Xn0, *H2, *WhT, *hb0, *hb1;
    cudaGetSymbolAddress((void**)&Xemb, g_Xemb);
    cudaGetSymbolAddress((void**)&Xz0, g_Xz0);
    cudaGetSymbolAddress((void**)&Xr0, g_Xr0);
    cudaGetSymbolAddress((void**)&Xn0, g_Xn0);
    cudaGetSymbolAddress((void**)&H2,  g_H2);
    cudaGetSymbolAddress((void**)&WhT, g_WhT);
    cudaGetSymbolAddress((void**)&hb0, g_hb0);
    cudaGetSymbolAddress((void**)&hb1, g_hb1);

    float* hout = nullptr;
    long long need = (long long)B_ * T_ * V_ + 2LL * B_ * S_;
    if ((long long)out_size >= need) hout = out + (size_t)B_ * T_ * V_;

    reset_k<<<1, 256>>>();
    prep_k<<<4608, 256>>>(Wz, Wr, Wn);
    embed_k<<<1024, 256>>>(x, emb);

    // layer-0 input projections (+bias baked in): [4096,1024] @ [1024,1024]
    dim3 gproj(S_ / 128, (T_ * B_) / 128);
    sgemm_bias<<<gproj, 256>>>(Xemb, Wz, bz, Xz0, T_ * B_, S_, E_, 0);
    sgemm_bias<<<gproj, 256>>>(Xemb, Wr, br, Xr0, T_ * B_, S_, E_, 0);
    sgemm_bias<<<gproj, 256>>>(Xemb, Wn, bn, Xn0, T_ * B_, S_, E_, 0);

    // layer-0 recurrence (H1 written over g_Xemb, which is free after proj0)
    gru_pass<<<NBLK, NTHR, smem>>>(Xz0, Xr0, Xn0, WhT, hb0, Xemb, 0u);

    // layer-1 input projections from H1 (+layer-1 bias). Wx1 = rows [0,E) of layer-1 block.
    const float* Wz1 = Wz + (size_t)(E_ + S_) * S_;
    const float* Wr1 = Wr + (size_t)(E_ + S_) * S_;
    const float* Wn1 = Wn + (size_t)(E_ + S_) * S_;
    sgemm_bias<<<gproj, 256>>>(Xemb, Wz1, bz + S_, Xz0, T_ * B_, S_, E_, 0);
    sgemm_bias<<<gproj, 256>>>(Xemb, Wr1, br + S_, Xr0, T_ * B_, S_, E_, 0);
    sgemm_bias<<<gproj, 256>>>(Xemb, Wn1, bn + S_, Xn0, T_ * B_, S_, E_, 0);

    // layer-1 recurrence
    gru_pass<<<NBLK, NTHR, smem>>>(Xz0, Xr0, Xn0, WhT + 3 * S_ * S_, hb1, H2, 2u * T_);

    // final vocab projection: [4096,1024] @ [1024,32000] + bias, rows remapped to [B,T,V]
    dim3 gout(V_ / 128, (T_ * B_) / 128);
    sgemm_bias<<<gout, 256>>>(H2, Wo, bo, out, T_ * B_, V_, S_, 1);

    if (hout) copy_h_k<<<(B_ * S_ + 255) / 256, 256>>>(hout);
}

// round 6
// speedup vs baseline: 2.1819x; 1.4300x over previous
#include <cuda_runtime.h>
#include <cuda_bf16.h>
#include <math.h>
#include <stdint.h>

#define B_ 16
#define T_ 256
#define S_ 1024
#define E_ 1024
#define V_ 32000
#define NBLK 148
#define NTHR 512
#define NC_ 16                        // K chunks of 64
#define STAGE_BYTES 65536             // Ahi/Alo/Bhi/Blo, 16 KB each

// ------------------ scratch (device globals; no allocation allowed) -------------
__device__ float g_Xemb[T_*B_*E_];      // embeddings; later reused as H1
__device__ float g_Xz0[T_*B_*S_];
__device__ float g_Xr0[T_*B_*S_];
__device__ float g_Xn0[T_*B_*S_];
__device__ float g_H2[T_*B_*S_];
__device__ float g_WhT[6*S_*S_];        // fp32 transposed hidden weights (recurrence)
__device__ float g_hb0[B_*S_];
__device__ float g_hb1[B_*S_];
__device__ float g_zbuf[B_*S_];
__device__ float g_rhbuf[B_*S_];
__device__ unsigned int g_flags[256];
// bf16 split operands for tensor-core GEMMs
__device__ uint16_t g_Ahi[T_*B_*E_];
__device__ uint16_t g_Alo[T_*B_*E_];
__device__ uint16_t g_Whi[6*S_*S_ + V_*S_];  // 6 gate input-weights [S,S] + WoT [V,S], K-major
__device__ uint16_t g_Wlo[6*S_*S_ + V_*S_];

// ------------------ PTX helpers --------------------------------------------------
__device__ __forceinline__ uint32_t smem_u32(const void* p) {
    uint32_t a;
    asm("{ .reg .u64 t; cvta.to.shared.u64 t, %1; cvt.u32.u64 %0, t; }" : "=r"(a) : "l"(p));
    return a;
}
__device__ __forceinline__ void cpa16(uint32_t s, const void* g) {
    asm volatile("cp.async.cg.shared.global [%0], [%1], 16;" :: "r"(s), "l"(g));
}
__device__ __forceinline__ void cpa_commit() { asm volatile("cp.async.commit_group;"); }
template <int N> __device__ __forceinline__ void cpa_wait() {
    asm volatile("cp.async.wait_group %0;" :: "n"(N));
}
#define LDSM4(r0, r1, r2, r3, a) \
    asm volatile("ldmatrix.sync.aligned.m8n8.x4.shared.b16 {%0,%1,%2,%3}, [%4];" \
        : "=r"(r0), "=r"(r1), "=r"(r2), "=r"(r3) : "r"(a))
#define MMA16816(d, a, b) \
    asm volatile("mma.sync.aligned.m16n8k16.row.col.f32.bf16.bf16.f32 " \
        "{%0,%1,%2,%3}, {%4,%5,%6,%7}, {%8,%9}, {%0,%1,%2,%3};" \
        : "+f"((d)[0]), "+f"((d)[1]), "+f"((d)[2]), "+f"((d)[3]) \
        : "r"((a)[0]), "r"((a)[1]), "r"((a)[2]), "r"((a)[3]), "r"((b)[0]), "r"((b)[1]))

// ------------------ small utility kernels ---------------------------------------
__global__ void reset_k() { if (threadIdx.x < 256) g_flags[threadIdx.x] = 0u; }

__global__ void embed_k(const int* __restrict__ x, const float* __restrict__ emb) {
    int idx = blockIdx.x * blockDim.x + threadIdx.x;
    const int total = T_ * B_ * (E_ / 4);
    const int stride = gridDim.x * blockDim.x;
    for (; idx < total; idx += stride) {
        int e4 = idx & (E_/4 - 1);
        int tb = idx >> 8;
        int t = tb >> 4, b = tb & 15;
        int tok = x[b * T_ + t];
        reinterpret_cast<float4*>(g_Xemb)[idx] =
            reinterpret_cast<const float4*>(emb)[(size_t)tok * (E_/4) + e4];
    }
}

__global__ void prep_k(const float* __restrict__ Wz, const float* __restrict__ Wr,
                       const float* __restrict__ Wn) {
    const int SS = S_ * S_;
    int idx = blockIdx.x * blockDim.x + threadIdx.x;
    const int stride = gridDim.x * blockDim.x;
    for (; idx < 6 * SS; idx += stride) {
        int k = idx & (S_ - 1);
        int c = (idx >> 10) & (S_ - 1);
        int t20 = idx >> 20;
        int j = t20 / 3, g = t20 - 3 * j;
        const float* W = (g == 0) ? Wz : (g == 1) ? Wr : Wn;
        g_WhT[idx] = W[((size_t)(j * (E_ + S_) + E_ + k)) * S_ + c];
    }
}

// fp32 -> bf16 hi/lo split of the activation matrix [T*B, E]
__global__ void convA_k(const float* __restrict__ src) {
    int i = blockIdx.x * blockDim.x + threadIdx.x;
    if (i < T_ * B_ * E_) {
        float x = src[i];
        __nv_bfloat16 h = __float2bfloat16(x);
        g_Ahi[i] = __bfloat16_as_ushort(h);
        g_Alo[i] = __bfloat16_as_ushort(__float2bfloat16(x - __bfloat162float(h)));
    }
}

// transpose + split: src [K rows, N cols] (ld = ldn)  ->  dst[n*K + k] hi/lo bf16
__global__ void convW_k(const float* __restrict__ src, int ldn,
                        uint16_t* __restrict__ dhi, uint16_t* __restrict__ dlo, int K) {
    __shared__ float smt[32][33];
    int n0 = blockIdx.x * 32, k0 = blockIdx.y * 32;
    int tx = threadIdx.x, ty = threadIdx.y;
    smt[ty][tx] = src[(size_t)(k0 + ty) * ldn + n0 + tx];
    __syncthreads();
    float x = smt[tx][ty];
    __nv_bfloat16 h = __float2bfloat16(x);
    size_t o = (size_t)(n0 + ty) * K + k0 + tx;
    dhi[o] = __bfloat16_as_ushort(h);
    dlo[o] = __bfloat16_as_ushort(__float2bfloat16(x - __bfloat162float(h)));
}

// ------------------ mma.sync split-bf16 GEMM -------------------------------------
// C[4096, Ntot] = A[4096,1024] @ B^T, B stored [Ntot,1024] K-major bf16 hi/lo.
// CTA tile 128(M) x 128(N), K-chunk 64, double-buffered cp.async.
// smem chunk swizzle: 128B rows of 8x16B chunks, chunk' = chunk ^ (row & 7).
__device__ __forceinline__ uint32_t sw_addr(uint32_t base, int row, int chunk) {
    return base + row * 128 + (((chunk ^ (row & 7)) & 7) << 4);
}

__device__ __forceinline__ void load_chunk(
    uint32_t sb, const uint16_t* __restrict__ Ah, const uint16_t* __restrict__ Al,
    const uint16_t* __restrict__ Bh, const uint16_t* __restrict__ Bl,
    int m0, int n0, int c, int tid)
{
    const int ko = c * 64;
#pragma unroll
    for (int it = 0; it < 4; it++) {
        int o = tid + it * 256;
        int row = o >> 3, ch = o & 7;
        uint32_t dst = sw_addr(sb, row, ch);
        const size_t goffA = (size_t)(m0 + row) * 1024 + ko + ch * 8;
        const size_t goffB = (size_t)(n0 + row) * 1024 + ko + ch * 8;
        cpa16(dst,         Ah + goffA);
        cpa16(dst + 16384, Al + goffA);
        cpa16(dst + 32768, Bh + goffB);
        cpa16(dst + 49152, Bl + goffB);
    }
}

__global__ __launch_bounds__(256, 1) void tc_gemm(
    const uint16_t* __restrict__ Ah, const uint16_t* __restrict__ Al,
    const uint16_t* __restrict__ Bh, const uint16_t* __restrict__ Bl,
    const float* __restrict__ bias, float* __restrict__ C, int Ntot, int remap)
{
    extern __shared__ char smem[];
    const uint32_t sbase = smem_u32(smem);
    const int tid = threadIdx.x;
    const int w = tid >> 5, lane = tid & 31;
    const int m0 = blockIdx.x * 128;     // grid.x = M/128 (fast-varying: B slice L2-shared per wave)
    const int n0 = blockIdx.y * 128;
    const int wm = (w & 1) * 64, wn = (w >> 1) * 32;

    float acc[4][4][4];
#pragma unroll
    for (int i = 0; i < 4; i++)
#pragma unroll
        for (int j = 0; j < 4; j++)
#pragma unroll
            for (int q = 0; q < 4; q++) acc[i][j][q] = 0.f;

    // ldmatrix lane-address components
    const int sub = lane >> 3, l7 = lane & 7;
    const int a_row_off = (sub & 1) * 8 + l7;     // A: rows (sub&1)*8, chunk (sub>>1)
    const int a_ch_off  = sub >> 1;
    const int b_row_off = (sub >> 1) * 8 + l7;    // B: rows (sub>>1)*8, chunk (sub&1)
    const int b_ch_off  = sub & 1;

    load_chunk(sbase, Ah, Al, Bh, Bl, m0, n0, 0, tid);
    cpa_commit();

    for (int c = 0; c < NC_; c++) {
        if (c + 1 < NC_) {
            load_chunk(sbase + ((c + 1) & 1) * STAGE_BYTES, Ah, Al, Bh, Bl, m0, n0, c + 1, tid);
            cpa_commit();
            cpa_wait<1>();
        } else {
            cpa_wait<0>();
        }
        __syncthreads();

        const uint32_t sAh = sbase + (c & 1) * STAGE_BYTES;
        const uint32_t sAl = sAh + 16384;
        const uint32_t sBh = sAh + 32768;
        const uint32_t sBl = sAh + 49152;

#pragma unroll
        for (int kk = 0; kk < 4; kk++) {
            uint32_t Afh[4][4], Afl[4][4], Bfh[4][2], Bfl[4][2];
#pragma unroll
            for (int mt = 0; mt < 4; mt++) {
                int row = wm + mt * 16 + a_row_off;
                int ch = kk * 2 + a_ch_off;
                LDSM4(Afh[mt][0], Afh[mt][1], Afh[mt][2], Afh[mt][3], sw_addr(sAh, row, ch));
                LDSM4(Afl[mt][0], Afl[mt][1], Afl[mt][2], Afl[mt][3], sw_addr(sAl, row, ch));
            }
#pragma unroll
            for (int pr = 0; pr < 2; pr++) {
                int row = wn + pr * 16 + b_row_off;
                int ch = kk * 2 + b_ch_off;
                LDSM4(Bfh[2*pr][0], Bfh[2*pr][1], Bfh[2*pr+1][0], Bfh[2*pr+1][1],
                      sw_addr(sBh, row, ch));
                LDSM4(Bfl[2*pr][0], Bfl[2*pr][1], Bfl[2*pr+1][0], Bfl[2*pr+1][1],
                      sw_addr(sBl, row, ch));
            }
#pragma unroll
            for (int mt = 0; mt < 4; mt++)
#pragma unroll
                for (int nt = 0; nt < 4; nt++) {
                    MMA16816(acc[mt][nt], Afh[mt], Bfh[nt]);
                    MMA16816(acc[mt][nt], Afh[mt], Bfl[nt]);
                    MMA16816(acc[mt][nt], Afl[mt], Bfh[nt]);
                }
        }
        __syncthreads();
    }

    // epilogue: lane holds C[r][2c],C[r][2c+1] (d0,d1) and C[r+8][..] (d2,d3)
    const int er = lane >> 2, ec = (lane & 3) * 2;
#pragma unroll
    for (int mt = 0; mt < 4; mt++) {
#pragma unroll
        for (int nt = 0; nt < 4; nt++) {
            int col = n0 + wn + nt * 8 + ec;
            float b0 = bias[col], b1 = bias[col + 1];
            int m1 = m0 + wm + mt * 16 + er;
            int m2 = m1 + 8;
            int r1 = remap ? ((m1 & 15) * T_ + (m1 >> 4)) : m1;
            int r2 = remap ? ((m2 & 15) * T_ + (m2 >> 4)) : m2;
            float2 v1 = make_float2(acc[mt][nt][0] + b0, acc[mt][nt][1] + b1);
            float2 v2 = make_float2(acc[mt][nt][2] + b0, acc[mt][nt][3] + b1);
            *reinterpret_cast<float2*>(C + (size_t)r1 * Ntot + col) = v1;
            *reinterpret_cast<float2*>(C + (size_t)r2 * Ntot + col) = v2;
        }
    }
}

// ------------------ persistent single-layer recurrence ---------------------------
__device__ __forceinline__ void flag_barrier(unsigned int e) {
    __syncthreads();
    if (threadIdx.x == 0) {
        __threadfence();
        *((volatile unsigned int*)&g_flags[blockIdx.x]) = e;
    }
    if (threadIdx.x < 32) {
        const int lane = threadIdx.x;
        for (;;) {
            bool ok = true;
            for (int i = lane; i < (int)gridDim.x; i += 32)
                ok &= (*((volatile const unsigned int*)&g_flags[i]) >= e);
            if (__all_sync(0xffffffffu, ok)) break;
            __nanosleep(200);
        }
        __threadfence();
    }
    __syncthreads();
}

__device__ __forceinline__ void load_sh(float* dst, const float* src, int tid, int nthr) {
    const float4* s4 = reinterpret_cast<const float4*>(src);
    float4* d4 = reinterpret_cast<float4*>(dst);
#pragma unroll
    for (int i = tid; i < B_ * S_ / 4; i += nthr) d4[i] = __ldcg(s4 + i);
}

__device__ __forceinline__ void dual_dot(const float* __restrict__ w0row,
                                         const float* __restrict__ w1row,
                                         const float* __restrict__ sh,
                                         int lane, float acc[32]) {
    const float4* w04 = reinterpret_cast<const float4*>(w0row);
    const float4* w14 = reinterpret_cast<const float4*>(w1row);
#pragma unroll
    for (int kk = 0; kk < 8; kk++) {
        float4 a = w04[kk * 32 + lane];
        float4 c = w14[kk * 32 + lane];
        int kb = (kk * 32 + lane) * 4;
#pragma unroll
        for (int b = 0; b < 16; b++) {
            float4 h = *reinterpret_cast<const float4*>(sh + b * S_ + kb);
            acc[b]      = fmaf(a.x, h.x, acc[b]);
            acc[b]      = fmaf(a.y, h.y, acc[b]);
            acc[b]      = fmaf(a.z, h.z, acc[b]);
            acc[b]      = fmaf(a.w, h.w, acc[b]);
            acc[16 + b] = fmaf(c.x, h.x, acc[16 + b]);
            acc[16 + b] = fmaf(c.y, h.y, acc[16 + b]);
            acc[16 + b] = fmaf(c.z, h.z, acc[16 + b]);
            acc[16 + b] = fmaf(c.w, h.w, acc[16 + b]);
        }
    }
}

__device__ __forceinline__ float reduce32(float acc[32], int lane) {
    int cnt = 32;
#pragma unroll
    for (int off = 16; off >= 1; off >>= 1) {
        const bool up = (lane & off) != 0;
        const int half = cnt >> 1;
#pragma unroll
        for (int i = 0; i < 16; i++) {
            if (i < half) {
                float send = up ? acc[i] : acc[i + half];
                float recv = __shfl_xor_sync(0xffffffffu, send, off);
                acc[i] = (up ? acc[i + half] : acc[i]) + recv;
            }
        }
        cnt = half;
    }
    return acc[0];
}

__global__ __launch_bounds__(NTHR, 1) void gru_pass(
    const float* __restrict__ Xz, const float* __restrict__ Xr,
    const float* __restrict__ Xn, const float* __restrict__ WhT,
    float* __restrict__ hbuf, float* __restrict__ Hseq, unsigned int ebase)
{
    extern __shared__ float sh[];
    float* shA = sh;
    float* shB = sh + B_ * S_;
    const int tid = threadIdx.x;
    const int lane = tid & 31;
    const int wib = tid >> 5;
    const int bid = blockIdx.x;
    const int pA = wib * NBLK + bid;

    for (int i = tid; i < B_ * S_; i += NTHR) shA[i] = 0.f;
    __syncthreads();

    for (int t = 0; t < T_; ++t) {
        if (pA < S_) {
            const float* w0 = WhT + ((size_t)0 * S_ + pA) * S_;
            const float* w1 = WhT + ((size_t)1 * S_ + pA) * S_;
            float acc[32];
#pragma unroll
            for (int i = 0; i < 32; i++) acc[i] = 0.f;
            dual_dot(w0, w1, shA, lane, acc);
            float s = reduce32(acc, lane);
            int b = lane & 15;
            const float* Xg = (lane < 16) ? Xz : Xr;
            float pre = __ldcg(&Xg[((size_t)t * B_ + b) * S_ + pA]) + s;
            float sg = 1.f / (1.f + __expf(-pre));
            if (lane < 16) __stcg(&g_zbuf[b * S_ + pA], sg);
            else           __stcg(&g_rhbuf[b * S_ + pA], sg * shA[b * S_ + pA]);
        }
        flag_barrier(ebase + 2 * t + 1);
        load_sh(shB, g_rhbuf, tid, NTHR);
        __syncthreads();

        if (pA < S_ / 2) {
            const int c0 = 2 * pA;
            const float* w0 = WhT + ((size_t)2 * S_ + c0) * S_;
            const float* w1 = WhT + ((size_t)2 * S_ + c0 + 1) * S_;
            float acc[32];
#pragma unroll
            for (int i = 0; i < 32; i++) acc[i] = 0.f;
            dual_dot(w0, w1, shB, lane, acc);
            float s = reduce32(acc, lane);
            int b = lane & 15;
            int col = c0 + (lane >> 4);
            float pre = __ldcg(&Xn[((size_t)t * B_ + b) * S_ + col]) + s;
            float n = tanhf(pre);
            float ho = shA[b * S_ + col];
            float z  = __ldcg(&g_zbuf[b * S_ + col]);
            float hn = ho + z * (n - ho);
            __stcg(&hbuf[b * S_ + col], hn);
            __stcg(&Hseq[((size_t)t * B_ + b) * S_ + col], hn);
        }
        flag_barrier(ebase + 2 * t + 2);
        load_sh(shA, hbuf, tid, NTHR);
        __syncthreads();
    }
}

__global__ void copy_h_k(float* __restrict__ hout) {
    int i = blockIdx.x * blockDim.x + threadIdx.x;
    if (i < B_ * S_) {
        hout[i]           = g_hb0[i];
        hout[B_ * S_ + i] = g_hb1[i];
    }
}

// ------------------ launch --------------------------------------------------------
extern "C" void kernel_launch(void* const* d_in, const int* in_sizes, int n_in,
                              void* d_out, int out_size) {
    const int*   x   = (const int*)  d_in[0];
    const float* emb = (const float*)d_in[1];
    const float* Wz  = (const float*)d_in[2];
    const float* bz  = (const float*)d_in[3];
    const float* Wr  = (const float*)d_in[4];
    const float* br  = (const float*)d_in[5];
    const float* Wn  = (const float*)d_in[6];
    const float* bn  = (const float*)d_in[7];
    const float* Wo  = (const float*)d_in[8];
    const float* bo  = (const float*)d_in[9];
    float* out = (float*)d_out;
    (void)in_sizes; (void)n_in;

    const int smem_rec = 2 * B_ * S_ * (int)sizeof(float);     // 128 KB
    const int smem_tc  = 2 * STAGE_BYTES;                       // 128 KB
    cudaFuncSetAttribute(gru_pass, cudaFuncAttributeMaxDynamicSharedMemorySize, smem_rec);
    cudaFuncSetAttribute(tc_gemm,  cudaFuncAttributeMaxDynamicSharedMemorySize, smem_tc);

    float *Xemb, *Xz0, *Xr0, *Xn0, *H2, *WhT, *hb0, *hb1;
    uint16_t *Ahi, *Alo, *Whi, *Wlo;
    cudaGetSymbolAddress((void**)&Xemb, g_Xemb);
    cudaGetSymbolAddress((void**)&Xz0, g_Xz0);
    cudaGetSymbolAddress((void**)&Xr0, g_Xr0);
    cudaGetSymbolAddress((void**)&Xn0, g_Xn0);
    cudaGetSymbolAddress((void**)&H2,  g_H2);
    cudaGetSymbolAddress((void**)&WhT, g_WhT);
    cudaGetSymbolAddress((void**)&hb0, g_hb0);
    cudaGetSymbolAddress((void**)&hb1, g_hb1);
    cudaGetSymbolAddress((void**)&Ahi, g_Ahi);
    cudaGetSymbolAddress((void**)&Alo, g_Alo);
    cudaGetSymbolAddress((void**)&Whi, g_Whi);
    cudaGetSymbolAddress((void**)&Wlo, g_Wlo);

    float* hout = nullptr;
    long long need = (long long)B_ * T_ * V_ + 2LL * B_ * S_;
    if ((long long)out_size >= need) hout = out + (size_t)B_ * T_ * V_;

    const size_t SS = (size_t)S_ * S_;

    reset_k<<<1, 256>>>();
    prep_k<<<4608, 256>>>(Wz, Wr, Wn);
    embed_k<<<1024, 256>>>(x, emb);

    // weight conversions: 6 input-side gate weights [S,S] + Wo [S,V] -> [N,K] bf16 hi/lo
    dim3 cb(32, 32);
    dim3 cgGate(S_ / 32, S_ / 32);
    convW_k<<<cgGate, cb>>>(Wz,                          S_, Whi + 0 * SS, Wlo + 0 * SS, S_);
    convW_k<<<cgGate, cb>>>(Wr,                          S_, Whi + 1 * SS, Wlo + 1 * SS, S_);
    convW_k<<<cgGate, cb>>>(Wn,                          S_, Whi + 2 * SS, Wlo + 2 * SS, S_);
    convW_k<<<cgGate, cb>>>(Wz + (size_t)(E_ + S_) * S_, S_, Whi + 3 * SS, Wlo + 3 * SS, S_);
    convW_k<<<cgGate, cb>>>(Wr + (size_t)(E_ + S_) * S_, S_, Whi + 4 * SS, Wlo + 4 * SS, S_);
    convW_k<<<cgGate, cb>>>(Wn + (size_t)(E_ + S_) * S_, S_, Whi + 5 * SS, Wlo + 5 * SS, S_);
    dim3 cgVoc(V_ / 32, S_ / 32);
    convW_k<<<cgVoc, cb>>>(Wo, V_, Whi + 6 * SS, Wlo + 6 * SS, S_);

    const int nA = T_ * B_ * E_;
    dim3 gproj((T_ * B_) / 128, S_ / 128);   // (32, 8), m fast-varying

    // layer-0 input projections (tensor core, bias baked in)
    convA_k<<<(nA + 255) / 256, 256>>>(Xemb);
    tc_gemm<<<gproj, 256, smem_tc>>>(Ahi, Alo, Whi + 0 * SS, Wlo + 0 * SS, bz, Xz0, S_, 0);
    tc_gemm<<<gproj, 256, smem_tc>>>(Ahi, Alo, Whi + 1 * SS, Wlo + 1 * SS, br, Xr0, S_, 0);
    tc_gemm<<<gproj, 256, smem_tc>>>(Ahi, Alo, Whi + 2 * SS, Wlo + 2 * SS, bn, Xn0, S_, 0);

    // layer-0 recurrence (H1 into g_Xemb)
    gru_pass<<<NBLK, NTHR, smem_rec>>>(Xz0, Xr0, Xn0, WhT, hb0, Xemb, 0u);

    // layer-1 input projections
    convA_k<<<(nA + 255) / 256, 256>>>(Xemb);
    tc_gemm<<<gproj, 256, smem_tc>>>(Ahi, Alo, Whi + 3 * SS, Wlo + 3 * SS, bz + S_, Xz0, S_, 0);
    tc_gemm<<<gproj, 256, smem_tc>>>(Ahi, Alo, Whi + 4 * SS, Wlo + 4 * SS, br + S_, Xr0, S_, 0);
    tc_gemm<<<gproj, 256, smem_tc>>>(Ahi, Alo, Whi + 5 * SS, Wlo + 5 * SS, bn + S_, Xn0, S_, 0);

    // layer-1 recurrence
    gru_pass<<<NBLK, NTHR, smem_rec>>>(Xz0, Xr0, Xn0, WhT + 3 * SS, hb1, H2, 2u * T_);

    // vocab projection (tensor core), rows remapped to [B, T, V]
    convA_k<<<(nA + 255) / 256, 256>>>(H2);
    dim3 gout((T_ * B_) / 128, V_ / 128);    // (32, 250), m fast-varying
    tc_gemm<<<gout, 256, smem_tc>>>(Ahi, Alo, Whi + 6 * SS, Wlo + 6 * SS, bo, out, V_, 1);

    if (hout) copy_h_k<<<(B_ * S_ + 255) / 256, 256>>>(hout);
}

// round 8
// speedup vs baseline: 2.2174x; 1.0163x over previous
#include <cuda_runtime.h>
#include <cuda_bf16.h>
#include <math.h>
#include <stdint.h>

#define B_ 16
#define T_ 256
#define S_ 1024
#define E_ 1024
#define V_ 32000
#define NBLK 148
#define NTHR 512
#define NC_ 16                        // K chunks of 64
#define STAGE_BYTES 65536             // Ahi/Alo/Bhi/Blo, 16 KB each

// ------------------ scratch (device globals; no allocation allowed) -------------
__device__ float g_Xemb[T_*B_*E_];      // embeddings; later reused as H1
__device__ float g_Xz0[T_*B_*S_];
__device__ float g_Xr0[T_*B_*S_];
__device__ float g_Xn0[T_*B_*S_];
__device__ float g_H2[T_*B_*S_];
__device__ float g_WhT[6*S_*S_];        // fp32 transposed hidden weights (recurrence)
__device__ float g_hb0[B_*S_];
__device__ float g_hb1[B_*S_];
__device__ float g_zbuf[B_*S_];
__device__ float g_rhbuf[B_*S_];
__device__ unsigned int g_flags[256];
// bf16 split operands for tensor-core GEMMs
__device__ uint16_t g_Ahi[T_*B_*E_];
__device__ uint16_t g_Alo[T_*B_*E_];
__device__ uint16_t g_Whi[6*S_*S_ + V_*S_];  // 6 gate input-weights [S,S] + WoT [V,S], K-major
__device__ uint16_t g_Wlo[6*S_*S_ + V_*S_];

// ------------------ PTX helpers --------------------------------------------------
__device__ __forceinline__ uint32_t smem_u32(const void* p) {
    uint32_t a;
    asm("{ .reg .u64 t; cvta.to.shared.u64 t, %1; cvt.u32.u64 %0, t; }" : "=r"(a) : "l"(p));
    return a;
}
__device__ __forceinline__ void cpa16(uint32_t s, const void* g) {
    asm volatile("cp.async.cg.shared.global [%0], [%1], 16;" :: "r"(s), "l"(g));
}
__device__ __forceinline__ void cpa_commit() { asm volatile("cp.async.commit_group;"); }
template <int N> __device__ __forceinline__ void cpa_wait() {
    asm volatile("cp.async.wait_group %0;" :: "n"(N));
}
#define LDSM4(r0, r1, r2, r3, a) \
    asm volatile("ldmatrix.sync.aligned.m8n8.x4.shared.b16 {%0,%1,%2,%3}, [%4];" \
        : "=r"(r0), "=r"(r1), "=r"(r2), "=r"(r3) : "r"(a))
#define MMA16816(d, a, b) \
    asm volatile("mma.sync.aligned.m16n8k16.row.col.f32.bf16.bf16.f32 " \
        "{%0,%1,%2,%3}, {%4,%5,%6,%7}, {%8,%9}, {%0,%1,%2,%3};" \
        : "+f"((d)[0]), "+f"((d)[1]), "+f"((d)[2]), "+f"((d)[3]) \
        : "r"((a)[0]), "r"((a)[1]), "r"((a)[2]), "r"((a)[3]), "r"((b)[0]), "r"((b)[1]))

// ------------------ small utility kernels ---------------------------------------
__global__ void reset_k() { if (threadIdx.x < 256) g_flags[threadIdx.x] = 0u; }

__global__ void embed_k(const int* __restrict__ x, const float* __restrict__ emb) {
    int idx = blockIdx.x * blockDim.x + threadIdx.x;
    const int total = T_ * B_ * (E_ / 4);
    const int stride = gridDim.x * blockDim.x;
    for (; idx < total; idx += stride) {
        int e4 = idx & (E_/4 - 1);
        int tb = idx >> 8;
        int t = tb >> 4, b = tb & 15;
        int tok = x[b * T_ + t];
        reinterpret_cast<float4*>(g_Xemb)[idx] =
            reinterpret_cast<const float4*>(emb)[(size_t)tok * (E_/4) + e4];
    }
}

__global__ void prep_k(const float* __restrict__ Wz, const float* __restrict__ Wr,
                       const float* __restrict__ Wn) {
    const int SS = S_ * S_;
    int idx = blockIdx.x * blockDim.x + threadIdx.x;
    const int stride = gridDim.x * blockDim.x;
    for (; idx < 6 * SS; idx += stride) {
        int k = idx & (S_ - 1);
        int c = (idx >> 10) & (S_ - 1);
        int t20 = idx >> 20;
        int j = t20 / 3, g = t20 - 3 * j;
        const float* W = (g == 0) ? Wz : (g == 1) ? Wr : Wn;
        g_WhT[idx] = W[((size_t)(j * (E_ + S_) + E_ + k)) * S_ + c];
    }
}

// fp32 -> bf16 hi/lo split of the activation matrix [T*B, E]
__global__ void convA_k(const float* __restrict__ src) {
    int i = blockIdx.x * blockDim.x + threadIdx.x;
    if (i < T_ * B_ * E_) {
        float x = src[i];
        __nv_bfloat16 h = __float2bfloat16(x);
        g_Ahi[i] = __bfloat16_as_ushort(h);
        g_Alo[i] = __bfloat16_as_ushort(__float2bfloat16(x - __bfloat162float(h)));
    }
}

// transpose + split: src [K rows, N cols] (ld = ldn)  ->  dst[n*K + k] hi/lo bf16
__global__ void convW_k(const float* __restrict__ src, int ldn,
                        uint16_t* __restrict__ dhi, uint16_t* __restrict__ dlo, int K) {
    __shared__ float smt[32][33];
    int n0 = blockIdx.x * 32, k0 = blockIdx.y * 32;
    int tx = threadIdx.x, ty = threadIdx.y;
    smt[ty][tx] = src[(size_t)(k0 + ty) * ldn + n0 + tx];
    __syncthreads();
    float x = smt[tx][ty];
    __nv_bfloat16 h = __float2bfloat16(x);
    size_t o = (size_t)(n0 + ty) * K + k0 + tx;
    dhi[o] = __bfloat16_as_ushort(h);
    dlo[o] = __bfloat16_as_ushort(__float2bfloat16(x - __bfloat162float(h)));
}

// ------------------ mma.sync split-bf16 GEMM -------------------------------------
// C[4096, Ntot] = A[4096,1024] @ B^T, B stored [Ntot,1024] K-major bf16 hi/lo.
// CTA tile 128(M) x 128(N), K-chunk 64, double-buffered cp.async.
// smem chunk swizzle: 128B rows of 8x16B chunks, chunk' = chunk ^ (row & 7).
__device__ __forceinline__ uint32_t sw_addr(uint32_t base, int row, int chunk) {
    return base + row * 128 + (((chunk ^ (row & 7)) & 7) << 4);
}

__device__ __forceinline__ void load_chunk(
    uint32_t sb, const uint16_t* __restrict__ Ah, const uint16_t* __restrict__ Al,
    const uint16_t* __restrict__ Bh, const uint16_t* __restrict__ Bl,
    int m0, int n0, int c, int tid)
{
    const int ko = c * 64;
#pragma unroll
    for (int it = 0; it < 4; it++) {
        int o = tid + it * 256;
        int row = o >> 3, ch = o & 7;
        uint32_t dst = sw_addr(sb, row, ch);
        const size_t goffA = (size_t)(m0 + row) * 1024 + ko + ch * 8;
        const size_t goffB = (size_t)(n0 + row) * 1024 + ko + ch * 8;
        cpa16(dst,         Ah + goffA);
        cpa16(dst + 16384, Al + goffA);
        cpa16(dst + 32768, Bh + goffB);
        cpa16(dst + 49152, Bl + goffB);
    }
}

__global__ __launch_bounds__(256, 1) void tc_gemm(
    const uint16_t* __restrict__ Ah, const uint16_t* __restrict__ Al,
    const uint16_t* __restrict__ Bh, const uint16_t* __restrict__ Bl,
    const float* __restrict__ bias, float* __restrict__ C, int Ntot, int remap)
{
    extern __shared__ char smem[];
    const uint32_t sbase = smem_u32(smem);
    const int tid = threadIdx.x;
    const int w = tid >> 5, lane = tid & 31;
    const int m0 = blockIdx.x * 128;     // grid.x = M/128 (fast-varying: B slice L2-shared per wave)
    const int n0 = blockIdx.y * 128;
    const int wm = (w & 1) * 64, wn = (w >> 1) * 32;

    float acc[4][4][4];
#pragma unroll
    for (int i = 0; i < 4; i++)
#pragma unroll
        for (int j = 0; j < 4; j++)
#pragma unroll
            for (int q = 0; q < 4; q++) acc[i][j][q] = 0.f;

    // ldmatrix lane-address components
    const int sub = lane >> 3, l7 = lane & 7;
    const int a_row_off = (sub & 1) * 8 + l7;     // A: rows (sub&1)*8, chunk (sub>>1)
    const int a_ch_off  = sub >> 1;
    const int b_row_off = (sub >> 1) * 8 + l7;    // B: rows (sub>>1)*8, chunk (sub&1)
    const int b_ch_off  = sub & 1;

    load_chunk(sbase, Ah, Al, Bh, Bl, m0, n0, 0, tid);
    cpa_commit();

    for (int c = 0; c < NC_; c++) {
        if (c + 1 < NC_) {
            load_chunk(sbase + ((c + 1) & 1) * STAGE_BYTES, Ah, Al, Bh, Bl, m0, n0, c + 1, tid);
            cpa_commit();
            cpa_wait<1>();
        } else {
            cpa_wait<0>();
        }
        __syncthreads();

        const uint32_t sAh = sbase + (c & 1) * STAGE_BYTES;
        const uint32_t sAl = sAh + 16384;
        const uint32_t sBh = sAh + 32768;
        const uint32_t sBl = sAh + 49152;

#pragma unroll
        for (int kk = 0; kk < 4; kk++) {
            uint32_t Afh[4][4], Afl[4][4], Bfh[4][2], Bfl[4][2];
#pragma unroll
            for (int mt = 0; mt < 4; mt++) {
                int row = wm + mt * 16 + a_row_off;
                int ch = kk * 2 + a_ch_off;
                LDSM4(Afh[mt][0], Afh[mt][1], Afh[mt][2], Afh[mt][3], sw_addr(sAh, row, ch));
                LDSM4(Afl[mt][0], Afl[mt][1], Afl[mt][2], Afl[mt][3], sw_addr(sAl, row, ch));
            }
#pragma unroll
            for (int pr = 0; pr < 2; pr++) {
                int row = wn + pr * 16 + b_row_off;
                int ch = kk * 2 + b_ch_off;
                LDSM4(Bfh[2*pr][0], Bfh[2*pr][1], Bfh[2*pr+1][0], Bfh[2*pr+1][1],
                      sw_addr(sBh, row, ch));
                LDSM4(Bfl[2*pr][0], Bfl[2*pr][1], Bfl[2*pr+1][0], Bfl[2*pr+1][1],
                      sw_addr(sBl, row, ch));
            }
#pragma unroll
            for (int mt = 0; mt < 4; mt++)
#pragma unroll
                for (int nt = 0; nt < 4; nt++) {
                    MMA16816(acc[mt][nt], Afh[mt], Bfh[nt]);
                    MMA16816(acc[mt][nt], Afh[mt], Bfl[nt]);
                    MMA16816(acc[mt][nt], Afl[mt], Bfh[nt]);
                }
        }
        __syncthreads();
    }

    // epilogue: lane holds C[r][2c],C[r][2c+1] (d0,d1) and C[r+8][..] (d2,d3)
    const int er = lane >> 2, ec = (lane & 3) * 2;
#pragma unroll
    for (int mt = 0; mt < 4; mt++) {
#pragma unroll
        for (int nt = 0; nt < 4; nt++) {
            int col = n0 + wn + nt * 8 + ec;
            float b0 = bias[col], b1 = bias[col + 1];
            int m1 = m0 + wm + mt * 16 + er;
            int m2 = m1 + 8;
            int r1 = remap ? ((m1 & 15) * T_ + (m1 >> 4)) : m1;
            int r2 = remap ? ((m2 & 15) * T_ + (m2 >> 4)) : m2;
            float2 v1 = make_float2(acc[mt][nt][0] + b0, acc[mt][nt][1] + b1);
            float2 v2 = make_float2(acc[mt][nt][2] + b0, acc[mt][nt][3] + b1);
            *reinterpret_cast<float2*>(C + (size_t)r1 * Ntot + col) = v1;
            *reinterpret_cast<float2*>(C + (size_t)r2 * Ntot + col) = v2;
        }
    }
}

// ------------------ persistent single-layer recurrence ---------------------------
__device__ __forceinline__ void flag_barrier(unsigned int e) {
    __syncthreads();
    if (threadIdx.x == 0) {
        __threadfence();
        *((volatile unsigned int*)&g_flags[blockIdx.x]) = e;
    }
    if (threadIdx.x < 32) {
        const int lane = threadIdx.x;
        for (;;) {
            bool ok = true;
            for (int i = lane; i < (int)gridDim.x; i += 32)
                ok &= (*((volatile const unsigned int*)&g_flags[i]) >= e);
            if (__all_sync(0xffffffffu, ok)) break;
            __nanosleep(200);
        }
        __threadfence();
    }
    __syncthreads();
}

__device__ __forceinline__ void load_sh(float* dst, const float* src, int tid, int nthr) {
    const float4* s4 = reinterpret_cast<const float4*>(src);
    float4* d4 = reinterpret_cast<float4*>(dst);
#pragma unroll
    for (int i = tid; i < B_ * S_ / 4; i += nthr) d4[i] = __ldcg(s4 + i);
}

__device__ __forceinline__ void dual_dot(const float* __restrict__ w0row,
                                         const float* __restrict__ w1row,
                                         const float* __restrict__ sh,
                                         int lane, float acc[32]) {
    const float4* w04 = reinterpret_cast<const float4*>(w0row);
    const float4* w14 = reinterpret_cast<const float4*>(w1row);
#pragma unroll
    for (int kk = 0; kk < 8; kk++) {
        float4 a = w04[kk * 32 + lane];
        float4 c = w14[kk * 32 + lane];
        int kb = (kk * 32 + lane) * 4;
#pragma unroll
        for (int b = 0; b < 16; b++) {
            float4 h = *reinterpret_cast<const float4*>(sh + b * S_ + kb);
            acc[b]      = fmaf(a.x, h.x, acc[b]);
            acc[b]      = fmaf(a.y, h.y, acc[b]);
            acc[b]      = fmaf(a.z, h.z, acc[b]);
            acc[b]      = fmaf(a.w, h.w, acc[b]);
            acc[16 + b] = fmaf(c.x, h.x, acc[16 + b]);
            acc[16 + b] = fmaf(c.y, h.y, acc[16 + b]);
            acc[16 + b] = fmaf(c.z, h.z, acc[16 + b]);
            acc[16 + b] = fmaf(c.w, h.w, acc[16 + b]);
        }
    }
}

__device__ __forceinline__ float reduce32(float acc[32], int lane) {
    int cnt = 32;
#pragma unroll
    for (int off = 16; off >= 1; off >>= 1) {
        const bool up = (lane & off) != 0;
        const int half = cnt >> 1;
#pragma unroll
        for (int i = 0; i < 16; i++) {
            if (i < half) {
                float send = up ? acc[i] : acc[i + half];
                float recv = __shfl_xor_sync(0xffffffffu, send, off);
                acc[i] = (up ? acc[i + half] : acc[i]) + recv;
            }
        }
        cnt = half;
    }
    return acc[0];
}

__global__ __launch_bounds__(NTHR, 1) void gru_pass(
    const float* __restrict__ Xz, const float* __restrict__ Xr,
    const float* __restrict__ Xn, const float* __restrict__ WhT,
    float* __restrict__ hbuf, float* __restrict__ Hseq, unsigned int ebase)
{
    extern __shared__ float sh[];
    float* shA = sh;
    float* shB = sh + B_ * S_;
    const int tid = threadIdx.x;
    const int lane = tid & 31;
    const int wib = tid >> 5;
    const int bid = blockIdx.x;
    const int pA = wib * NBLK + bid;

    for (int i = tid; i < B_ * S_; i += NTHR) shA[i] = 0.f;
    __syncthreads();

    for (int t = 0; t < T_; ++t) {
        if (pA < S_) {
            const float* w0 = WhT + ((size_t)0 * S_ + pA) * S_;
            const float* w1 = WhT + ((size_t)1 * S_ + pA) * S_;
            float acc[32];
#pragma unroll
            for (int i = 0; i < 32; i++) acc[i] = 0.f;
            dual_dot(w0, w1, shA, lane, acc);
            float s = reduce32(acc, lane);
            int b = lane & 15;
            const float* Xg = (lane < 16) ? Xz : Xr;
            float pre = __ldcg(&Xg[((size_t)t * B_ + b) * S_ + pA]) + s;
            float sg = 1.f / (1.f + __expf(-pre));
            if (lane < 16) __stcg(&g_zbuf[b * S_ + pA], sg);
            else           __stcg(&g_rhbuf[b * S_ + pA], sg * shA[b * S_ + pA]);
        }
        flag_barrier(ebase + 2 * t + 1);
        load_sh(shB, g_rhbuf, tid, NTHR);
        __syncthreads();

        if (pA < S_ / 2) {
            const int c0 = 2 * pA;
            const float* w0 = WhT + ((size_t)2 * S_ + c0) * S_;
            const float* w1 = WhT + ((size_t)2 * S_ + c0 + 1) * S_;
            float acc[32];
#pragma unroll
            for (int i = 0; i < 32; i++) acc[i] = 0.f;
            dual_dot(w0, w1, shB, lane, acc);
            float s = reduce32(acc, lane);
            int b = lane & 15;
            int col = c0 + (lane >> 4);
            float pre = __ldcg(&Xn[((size_t)t * B_ + b) * S_ + col]) + s;
            float n = tanhf(pre);
            float ho = shA[b * S_ + col];
            float z  = __ldcg(&g_zbuf[b * S_ + col]);
            float hn = ho + z * (n - ho);
            __stcg(&hbuf[b * S_ + col], hn);
            __stcg(&Hseq[((size_t)t * B_ + b) * S_ + col], hn);
        }
        flag_barrier(ebase + 2 * t + 2);
        load_sh(shA, hbuf, tid, NTHR);
        __syncthreads();
    }
}

__global__ void copy_h_k(float* __restrict__ hout) {
    int i = blockIdx.x * blockDim.x + threadIdx.x;
    if (i < B_ * S_) {
        hout[i]           = g_hb0[i];
        hout[B_ * S_ + i] = g_hb1[i];
    }
}

// ------------------ launch --------------------------------------------------------
extern "C" void kernel_launch(void* const* d_in, const int* in_sizes, int n_in,
                              void* d_out, int out_size) {
    const int*   x   = (const int*)  d_in[0];
    const float* emb = (const float*)d_in[1];
    const float* Wz  = (const float*)d_in[2];
    const float* bz  = (const float*)d_in[3];
    const float* Wr  = (const float*)d_in[4];
    const float* br  = (const float*)d_in[5];
    const float* Wn  = (const float*)d_in[6];
    const float* bn  = (const float*)d_in[7];
    const float* Wo  = (const float*)d_in[8];
    const float* bo  = (const float*)d_in[9];
    float* out = (float*)d_out;
    (void)in_sizes; (void)n_in;

    const int smem_rec = 2 * B_ * S_ * (int)sizeof(float);     // 128 KB
    const int smem_tc  = 2 * STAGE_BYTES;                       // 128 KB
    cudaFuncSetAttribute(gru_pass, cudaFuncAttributeMaxDynamicSharedMemorySize, smem_rec);
    cudaFuncSetAttribute(tc_gemm,  cudaFuncAttributeMaxDynamicSharedMemorySize, smem_tc);

    float *Xemb, *Xz0, *Xr0, *Xn0, *H2, *WhT, *hb0, *hb1;
    uint16_t *Ahi, *Alo, *Whi, *Wlo;
    cudaGetSymbolAddress((void**)&Xemb, g_Xemb);
    cudaGetSymbolAddress((void**)&Xz0, g_Xz0);
    cudaGetSymbolAddress((void**)&Xr0, g_Xr0);
    cudaGetSymbolAddress((void**)&Xn0, g_Xn0);
    cudaGetSymbolAddress((void**)&H2,  g_H2);
    cudaGetSymbolAddress((void**)&WhT, g_WhT);
    cudaGetSymbolAddress((void**)&hb0, g_hb0);
    cudaGetSymbolAddress((void**)&hb1, g_hb1);
    cudaGetSymbolAddress((void**)&Ahi, g_Ahi);
    cudaGetSymbolAddress((void**)&Alo, g_Alo);
    cudaGetSymbolAddress((void**)&Whi, g_Whi);
    cudaGetSymbolAddress((void**)&Wlo, g_Wlo);

    float* hout = nullptr;
    long long need = (long long)B_ * T_ * V_ + 2LL * B_ * S_;
    if ((long long)out_size >= need) hout = out + (size_t)B_ * T_ * V_;

    const size_t SS = (size_t)S_ * S_;

    reset_k<<<1, 256>>>();
    prep_k<<<4608, 256>>>(Wz, Wr, Wn);
    embed_k<<<1024, 256>>>(x, emb);

    // weight conversions: 6 input-side gate weights [S,S] + Wo [S,V] -> [N,K] bf16 hi/lo
    dim3 cb(32, 32);
    dim3 cgGate(S_ / 32, S_ / 32);
    convW_k<<<cgGate, cb>>>(Wz,                          S_, Whi + 0 * SS, Wlo + 0 * SS, S_);
    convW_k<<<cgGate, cb>>>(Wr,                          S_, Whi + 1 * SS, Wlo + 1 * SS, S_);
    convW_k<<<cgGate, cb>>>(Wn,                          S_, Whi + 2 * SS, Wlo + 2 * SS, S_);
    convW_k<<<cgGate, cb>>>(Wz + (size_t)(E_ + S_) * S_, S_, Whi + 3 * SS, Wlo + 3 * SS, S_);
    convW_k<<<cgGate, cb>>>(Wr + (size_t)(E_ + S_) * S_, S_, Whi + 4 * SS, Wlo + 4 * SS, S_);
    convW_k<<<cgGate, cb>>>(Wn + (size_t)(E_ + S_) * S_, S_, Whi + 5 * SS, Wlo + 5 * SS, S_);
    dim3 cgVoc(V_ / 32, S_ / 32);
    convW_k<<<cgVoc, cb>>>(Wo, V_, Whi + 6 * SS, Wlo + 6 * SS, S_);

    const int nA = T_ * B_ * E_;
    dim3 gproj((T_ * B_) / 128, S_ / 128);   // (32, 8), m fast-varying

    // layer-0 input projections (tensor core, bias baked in)
    convA_k<<<(nA + 255) / 256, 256>>>(Xemb);
    tc_gemm<<<gproj, 256, smem_tc>>>(Ahi, Alo, Whi + 0 * SS, Wlo + 0 * SS, bz, Xz0, S_, 0);
    tc_gemm<<<gproj, 256, smem_tc>>>(Ahi, Alo, Whi + 1 * SS, Wlo + 1 * SS, br, Xr0, S_, 0);
    tc_gemm<<<gproj, 256, smem_tc>>>(Ahi, Alo, Whi + 2 * SS, Wlo + 2 * SS, bn, Xn0, S_, 0);

    // layer-0 recurrence (H1 into g_Xemb)
    gru_pass<<<NBLK, NTHR, smem_rec>>>(Xz0, Xr0, Xn0, WhT, hb0, Xemb, 0u);

    // layer-1 input projections
    convA_k<<<(nA + 255) / 256, 256>>>(Xemb);
    tc_gemm<<<gproj, 256, smem_tc>>>(Ahi, Alo, Whi + 3 * SS, Wlo + 3 * SS, bz + S_, Xz0, S_, 0);
    tc_gemm<<<gproj, 256, smem_tc>>>(Ahi, Alo, Whi + 4 * SS, Wlo + 4 * SS, br + S_, Xr0, S_, 0);
    tc_gemm<<<gproj, 256, smem_tc>>>(Ahi, Alo, Whi + 5 * SS, Wlo + 5 * SS, bn + S_, Xn0, S_, 0);

    // layer-1 recurrence
    gru_pass<<<NBLK, NTHR, smem_rec>>>(Xz0, Xr0, Xn0, WhT + 3 * SS, hb1, H2, 2u * T_);

    // vocab projection (tensor core), rows remapped to [B, T, V]
    convA_k<<<(nA + 255) / 256, 256>>>(H2);
    dim3 gout((T_ * B_) / 128, V_ / 128);    // (32, 250), m fast-varying
    tc_gemm<<<gout, 256, smem_tc>>>(Ahi, Alo, Whi + 6 * SS, Wlo + 6 * SS, bo, out, V_, 1);

    if (hout) copy_h_k<<<(B_ * S_ + 255) / 256, 256>>>(hout);
}